// round 1
// baseline (speedup 1.0000x reference)
#include <cuda_runtime.h>
#include <math.h>

// ---------------- scratch (device globals; no allocation allowed) ----------------
__device__ float g_s  [256*256*64];
__device__ float g_c2 [128*128*256];
__device__ float g_c3 [64*64*512];
__device__ float g_c4 [32*32*1024];
__device__ float g_c5 [16*16*2048];
__device__ float g_p5 [16*16*256];
__device__ float g_p4 [32*32*256];
__device__ float g_p3 [64*64*256];
__device__ float g_p3o[64*64*256];
__device__ float g_t  [64*64*256];
__device__ float g_sc [64*64];

// ---------------- generic implicit-GEMM conv (NHWC, HWIO, SAME) ----------------
// M = HOUT*WOUT pixels, N = COUT, K = KS*KS*CIN. Requires M%64==0, COUT%64==0,
// CIN%16==0 (true for every live layer here).
template<int KS, int STRIDE, int HIN, int WIN, int CIN, int COUT, bool RELU, bool ADDUP2>
__global__ __launch_bounds__(256) void conv_gemm_k(
    const float* __restrict__ in, const float* __restrict__ wgt,
    const float* __restrict__ up, float* __restrict__ out)
{
    constexpr int HOUT = (HIN + STRIDE - 1) / STRIDE;
    constexpr int WOUT = (WIN + STRIDE - 1) / STRIDE;
    constexpr int PTOT = ((HOUT - 1) * STRIDE + KS - HIN) > 0 ? ((HOUT - 1) * STRIDE + KS - HIN) : 0;
    constexpr int PAD  = PTOT / 2;
    constexpr int K    = KS * KS * CIN;

    __shared__ float As[16][64];   // [k][pixel]
    __shared__ float Bs[16][64];   // [k][cout]

    const int tid = threadIdx.x;
    const int bm = blockIdx.x * 64;
    const int bn = blockIdx.y * 64;

    // A-tile loader mapping: each thread loads one float4 (4 consecutive ci)
    const int a_m  = tid >> 2;           // 0..63 pixel within tile
    const int a_k4 = (tid & 3) << 2;     // 0,4,8,12 k-offset within chunk
    const int am   = bm + a_m;
    const int aoy  = am / WOUT;
    const int aox  = am % WOUT;

    // B-tile loader mapping
    const int b_k  = tid >> 4;           // 0..15
    const int b_n4 = (tid & 15) << 2;    // 0..60

    // compute mapping: 16x16 thread grid, 4x4 micro-tile
    const int tr4 = (tid >> 4) << 2;
    const int tc4 = (tid & 15) << 2;

    float acc[4][4] = {};

    for (int k0 = 0; k0 < K; k0 += 16) {
        const int kq  = k0 / CIN;        // (ky*KS+kx), constant within chunk (CIN%16==0)
        const int cib = k0 % CIN;
        const int ky  = kq / KS;
        const int kx  = kq % KS;

        // load A (im2col on the fly)
        {
            const int iy = aoy * STRIDE + ky - PAD;
            const int ix = aox * STRIDE + kx - PAD;
            float4 v = make_float4(0.f, 0.f, 0.f, 0.f);
            if (iy >= 0 && iy < HIN && ix >= 0 && ix < WIN)
                v = *reinterpret_cast<const float4*>(in + ((size_t)(iy * WIN + ix) * CIN + cib + a_k4));
            As[a_k4 + 0][a_m] = v.x;
            As[a_k4 + 1][a_m] = v.y;
            As[a_k4 + 2][a_m] = v.z;
            As[a_k4 + 3][a_m] = v.w;
        }
        // load B (weights are [ky][kx][ci][co] -> row (k0+b_k), cols contiguous)
        {
            const float4 w4 = *reinterpret_cast<const float4*>(
                wgt + (size_t)(k0 + b_k) * COUT + bn + b_n4);
            Bs[b_k][b_n4 + 0] = w4.x;
            Bs[b_k][b_n4 + 1] = w4.y;
            Bs[b_k][b_n4 + 2] = w4.z;
            Bs[b_k][b_n4 + 3] = w4.w;
        }
        __syncthreads();

        #pragma unroll
        for (int kk = 0; kk < 16; kk++) {
            const float4 a = *reinterpret_cast<const float4*>(&As[kk][tr4]);
            const float4 b = *reinterpret_cast<const float4*>(&Bs[kk][tc4]);
            const float av[4] = {a.x, a.y, a.z, a.w};
            const float bv[4] = {b.x, b.y, b.z, b.w};
            #pragma unroll
            for (int i = 0; i < 4; i++)
                #pragma unroll
                for (int j = 0; j < 4; j++)
                    acc[i][j] = fmaf(av[i], bv[j], acc[i][j]);
        }
        __syncthreads();
    }

    // epilogue
    #pragma unroll
    for (int i = 0; i < 4; i++) {
        const int m  = bm + tr4 + i;
        const int oy = m / WOUT;
        const int ox = m % WOUT;
        float4 r = make_float4(acc[i][0], acc[i][1], acc[i][2], acc[i][3]);
        if (ADDUP2) {
            const float4 u = *reinterpret_cast<const float4*>(
                up + ((size_t)((oy >> 1) * (WOUT >> 1) + (ox >> 1)) * COUT + bn + tc4));
            r.x += u.x; r.y += u.y; r.z += u.z; r.w += u.w;
        }
        if (RELU) {
            r.x = fmaxf(r.x, 0.f); r.y = fmaxf(r.y, 0.f);
            r.z = fmaxf(r.z, 0.f); r.w = fmaxf(r.w, 0.f);
        }
        *reinterpret_cast<float4*>(out + (size_t)m * COUT + bn + tc4) = r;
    }
}

// ---------------- stem: 7x7 s2, Cin=3 -> 64, relu ----------------
// blockDim (64,8) = 512 threads; each block does 16 output pixels; weights in smem.
__global__ __launch_bounds__(512) void stem_kernel(
    const float* __restrict__ in, const float* __restrict__ w, float* __restrict__ out)
{
    __shared__ float ws[7*7*3*64];
    for (int i = threadIdx.y * 64 + threadIdx.x; i < 7*7*3*64; i += 512)
        ws[i] = w[i];
    __syncthreads();

    const int co = threadIdx.x;
    #pragma unroll
    for (int pp = 0; pp < 2; pp++) {
        const int p  = blockIdx.x * 16 + threadIdx.y * 2 + pp;
        const int oy = p >> 8;
        const int ox = p & 255;
        float acc = 0.f;
        #pragma unroll
        for (int ky = 0; ky < 7; ky++) {
            const int iy = oy * 2 + ky - 2;
            if (iy < 0 || iy >= 512) continue;
            #pragma unroll
            for (int kx = 0; kx < 7; kx++) {
                const int ix = ox * 2 + kx - 2;
                if (ix < 0 || ix >= 512) continue;
                const float* ip = in + (size_t)(iy * 512 + ix) * 3;
                const float* wp = ws + ((ky * 7 + kx) * 3) * 64 + co;
                acc = fmaf(ip[0], wp[0],   acc);
                acc = fmaf(ip[1], wp[64],  acc);
                acc = fmaf(ip[2], wp[128], acc);
            }
        }
        out[(size_t)p * 64 + co] = fmaxf(acc, 0.f);
    }
}

// ---------------- obj head (1x1, COUT=1) + sigmoid ----------------
// warp per pixel; 256-channel dot product.
__global__ __launch_bounds__(256) void obj_kernel(
    const float* __restrict__ t, const float* __restrict__ wobj, float* __restrict__ scores)
{
    const int p = blockIdx.x * 8 + (threadIdx.x >> 5);
    const int lane = threadIdx.x & 31;
    const float* tp = t + (size_t)p * 256;
    float acc = 0.f;
    #pragma unroll
    for (int c = 0; c < 256; c += 32)
        acc = fmaf(tp[c + lane], wobj[c + lane], acc);
    #pragma unroll
    for (int off = 16; off > 0; off >>= 1)
        acc += __shfl_xor_sync(0xFFFFFFFFu, acc, off);
    if (lane == 0)
        scores[p] = 1.f / (1.f + expf(-acc));
}

// ---------------- greedy NMS, 100 iterations, 4096 candidates ----------------
// single block, 1024 threads, 4 candidates per thread held in registers.
// Box mapping replicates the reference's meshgrid('xy') transpose:
//   k -> cy = (k & 63)/63, cx = (k >> 6)/63 ; box = clip([cy-.05, cx-.05, cy+.05, cx+.05], 0, 1)
__global__ __launch_bounds__(1024) void nms_kernel(
    const float* __restrict__ scores, float* __restrict__ out)
{
    const int tid = threadIdx.x;
    float sw[4], by1[4], bx1[4], by2[4], bx2[4], bar[4];
    #pragma unroll
    for (int t = 0; t < 4; t++) {
        const int j = tid + t * 1024;
        sw[t] = scores[j];
        const float cy = (float)(j & 63) * (1.0f / 63.0f);
        const float cx = (float)(j >> 6) * (1.0f / 63.0f);
        by1[t] = fmaxf(cy - 0.05f, 0.f);
        bx1[t] = fmaxf(cx - 0.05f, 0.f);
        by2[t] = fminf(cy + 0.05f, 1.f);
        bx2[t] = fminf(cx + 0.05f, 1.f);
        bar[t] = (by2[t] - by1[t]) * (bx2[t] - bx1[t]);
    }

    __shared__ float s_v[32];
    __shared__ int   s_i[32];
    __shared__ float s_bestv;
    __shared__ int   s_besti;

    const int lane = tid & 31;
    const int warp = tid >> 5;

    for (int it = 0; it < 100; it++) {
        // local argmax (tie-break: smallest global index, matching jnp.argmax)
        float bv = sw[0];
        int   bi = tid;
        #pragma unroll
        for (int t = 1; t < 4; t++) {
            const int j = tid + t * 1024;
            if (sw[t] > bv) { bv = sw[t]; bi = j; }  // j strictly increasing, '>' keeps min idx
        }
        #pragma unroll
        for (int off = 16; off > 0; off >>= 1) {
            const float ov = __shfl_down_sync(0xFFFFFFFFu, bv, off);
            const int   oi = __shfl_down_sync(0xFFFFFFFFu, bi, off);
            if (ov > bv || (ov == bv && oi < bi)) { bv = ov; bi = oi; }
        }
        if (lane == 0) { s_v[warp] = bv; s_i[warp] = bi; }
        __syncthreads();
        if (warp == 0) {
            bv = s_v[lane]; bi = s_i[lane];
            #pragma unroll
            for (int off = 16; off > 0; off >>= 1) {
                const float ov = __shfl_down_sync(0xFFFFFFFFu, bv, off);
                const int   oi = __shfl_down_sync(0xFFFFFFFFu, bi, off);
                if (ov > bv || (ov == bv && oi < bi)) { bv = ov; bi = oi; }
            }
            if (lane == 0) { s_bestv = bv; s_besti = bi; }
        }
        __syncthreads();

        const float bestv = s_bestv;
        const int   besti = s_besti;
        // best box recomputed from index (deterministic, same formula)
        const float bcy = (float)(besti & 63) * (1.0f / 63.0f);
        const float bcx = (float)(besti >> 6) * (1.0f / 63.0f);
        const float y1b = fmaxf(bcy - 0.05f, 0.f);
        const float x1b = fmaxf(bcx - 0.05f, 0.f);
        const float y2b = fminf(bcy + 0.05f, 1.f);
        const float x2b = fminf(bcx + 0.05f, 1.f);
        const float areab = (y2b - y1b) * (x2b - x1b);
        const bool valid = bestv > -5e29f;   // NEG * 0.5

        if (tid == 0) {
            out[it * 4 + 0] = valid ? y1b : 0.f;
            out[it * 4 + 1] = valid ? x1b : 0.f;
            out[it * 4 + 2] = valid ? y2b : 0.f;
            out[it * 4 + 3] = valid ? x2b : 0.f;
            out[400 + it]   = valid ? bestv : 0.f;
        }

        // suppress
        #pragma unroll
        for (int t = 0; t < 4; t++) {
            const float yy1 = fmaxf(y1b, by1[t]);
            const float xx1 = fmaxf(x1b, bx1[t]);
            const float yy2 = fminf(y2b, by2[t]);
            const float xx2 = fminf(x2b, bx2[t]);
            const float inter = fmaxf(yy2 - yy1, 0.f) * fmaxf(xx2 - xx1, 0.f);
            const float iou = inter / (areab + bar[t] - inter + 1e-9f);
            if (iou > 0.5f) sw[t] = -1e30f;
        }
        __syncthreads();
    }
}

// ---------------- orchestration ----------------
extern "C" void kernel_launch(void* const* d_in, const int* in_sizes, int n_in,
                              void* d_out, int out_size)
{
    (void)in_sizes; (void)n_in; (void)out_size;
    const float* inp    = (const float*)d_in[0];
    const float* w_stem = (const float*)d_in[1];
    const float* w_c2   = (const float*)d_in[2];
    const float* w_c3   = (const float*)d_in[3];
    const float* w_c4   = (const float*)d_in[4];
    const float* w_c5   = (const float*)d_in[5];
    const float* l3     = (const float*)d_in[6];
    const float* l4     = (const float*)d_in[7];
    const float* l5     = (const float*)d_in[8];
    const float* o3     = (const float*)d_in[9];
    const float* w_rpn  = (const float*)d_in[12];
    const float* w_obj  = (const float*)d_in[13];
    float* out = (float*)d_out;

    void *p_s, *p_c2, *p_c3, *p_c4, *p_c5, *p_p5, *p_p4, *p_p3, *p_p3o, *p_t, *p_sc;
    cudaGetSymbolAddress(&p_s,   g_s);
    cudaGetSymbolAddress(&p_c2,  g_c2);
    cudaGetSymbolAddress(&p_c3,  g_c3);
    cudaGetSymbolAddress(&p_c4,  g_c4);
    cudaGetSymbolAddress(&p_c5,  g_c5);
    cudaGetSymbolAddress(&p_p5,  g_p5);
    cudaGetSymbolAddress(&p_p4,  g_p4);
    cudaGetSymbolAddress(&p_p3,  g_p3);
    cudaGetSymbolAddress(&p_p3o, g_p3o);
    cudaGetSymbolAddress(&p_t,   g_t);
    cudaGetSymbolAddress(&p_sc,  g_sc);
    float* s_   = (float*)p_s;
    float* c2   = (float*)p_c2;
    float* c3   = (float*)p_c3;
    float* c4   = (float*)p_c4;
    float* c5   = (float*)p_c5;
    float* p5   = (float*)p_p5;
    float* p4   = (float*)p_p4;
    float* p3   = (float*)p_p3;
    float* p3o  = (float*)p_p3o;
    float* tb   = (float*)p_t;
    float* sc   = (float*)p_sc;

    // backbone
    stem_kernel<<<4096, dim3(64, 8)>>>(inp, w_stem, s_);
    conv_gemm_k<3, 2, 256, 256,   64,  256, true,  false><<<dim3(256,  4), 256>>>(s_,  w_c2, nullptr, c2);
    conv_gemm_k<3, 2, 128, 128,  256,  512, true,  false><<<dim3( 64,  8), 256>>>(c2,  w_c3, nullptr, c3);
    conv_gemm_k<3, 2,  64,  64,  512, 1024, true,  false><<<dim3( 16, 16), 256>>>(c3,  w_c4, nullptr, c4);
    conv_gemm_k<3, 2,  32,  32, 1024, 2048, true,  false><<<dim3(  4, 32), 256>>>(c4,  w_c5, nullptr, c5);
    // FPN (only the p3 path is live downstream)
    conv_gemm_k<1, 1,  16,  16, 2048,  256, false, false><<<dim3(  4,  4), 256>>>(c5,  l5,   nullptr, p5);
    conv_gemm_k<1, 1,  32,  32, 1024,  256, false, true ><<<dim3( 16,  4), 256>>>(c4,  l4,   p5,      p4);
    conv_gemm_k<1, 1,  64,  64,  512,  256, false, true ><<<dim3( 64,  4), 256>>>(c3,  l3,   p4,      p3);
    conv_gemm_k<3, 1,  64,  64,  256,  256, false, false><<<dim3( 64,  4), 256>>>(p3,  o3,   nullptr, p3o);
    // RPN on p3 only (obj head is the only consumer; w_box / p4,p5 RPN are dead code)
    conv_gemm_k<3, 1,  64,  64,  256,  256, true,  false><<<dim3( 64,  4), 256>>>(p3o, w_rpn, nullptr, tb);
    obj_kernel<<<512, 256>>>(tb, w_obj, sc);
    // NMS -> final 500 floats (400 box coords + 100 scores)
    nms_kernel<<<1, 1024>>>(sc, out);
}

// round 2
// speedup vs baseline: 1.1167x; 1.1167x over previous
#include <cuda_runtime.h>
#include <math.h>

// ---------------- scratch (device globals; no allocation allowed) ----------------
__device__ float g_s  [256*256*64];
__device__ float g_c2 [128*128*256];
__device__ float g_c3 [64*64*512];
__device__ float g_c4 [32*32*1024];
__device__ float g_c5 [16*16*2048];
__device__ float g_p5 [16*16*256];
__device__ float g_p4 [32*32*256];
__device__ float g_p3 [64*64*256];
__device__ float g_p3o[64*64*256];
__device__ float g_t  [64*64*256];
__device__ float g_sc [64*64];
__device__ float g_c5p[2*256*2048];   // split-K partials for c5
__device__ float g_p5p[4*256*256];    // split-K partials for l5

// ---------------- implicit-GEMM conv (NHWC, HWIO, SAME), double-buffered ----------------
// M = HOUT*WOUT, N = COUT, K = KS*KS*CIN. 256 threads, 16x16 compute grid,
// micro-tile TM x TN = (BM/16) x (BN/16). BK = 16. Register-staged prefetch.
// Requires: M % BM == 0, COUT % BN == 0, CIN % 16 == 0, (K/SPLITK) % 16 == 0.
template<int KS, int STRIDE, int HIN, int WIN, int CIN, int COUT,
         bool RELU, bool ADDUP2, int BM, int BN, int SPLITK>
__global__ __launch_bounds__(256) void conv_gemm_k(
    const float* __restrict__ in, const float* __restrict__ wgt,
    const float* __restrict__ up, float* __restrict__ out)
{
    constexpr int HOUT = (HIN + STRIDE - 1) / STRIDE;
    constexpr int WOUT = (WIN + STRIDE - 1) / STRIDE;
    constexpr int PTOTC = (HOUT - 1) * STRIDE + KS - HIN;
    constexpr int PAD  = (PTOTC > 0 ? PTOTC : 0) / 2;
    constexpr int K    = KS * KS * CIN;
    constexpr int KSEG = K / SPLITK;
    constexpr int NCH  = KSEG / 16;
    constexpr int TM   = BM / 16;
    constexpr int TN   = BN / 16;
    constexpr int AQ   = BM / 64;     // float4 quads per thread for A
    constexpr int BQ   = BN / 64;     // float4 quads per thread for B
    constexpr int MTOT = HOUT * WOUT;

    __shared__ float As[2][16][BM];
    __shared__ float Bs[2][16][BN];

    const int tid = threadIdx.x;
    const int bm = blockIdx.x * BM;
    const int bn = blockIdx.y * BN;
    const int kbase = blockIdx.z * KSEG;

    // loader mappings (constant across chunks)
    int a_m[AQ], a_k4[AQ], aoy[AQ], aox[AQ];
    #pragma unroll
    for (int aq = 0; aq < AQ; aq++) {
        const int q = tid + aq * 256;
        a_m[aq]  = q >> 2;
        a_k4[aq] = (q & 3) << 2;
        const int am = bm + a_m[aq];
        aoy[aq] = am / WOUT;
        aox[aq] = am % WOUT;
    }
    int b_k[BQ], b_n4[BQ];
    #pragma unroll
    for (int bq = 0; bq < BQ; bq++) {
        const int q = tid + bq * 256;
        b_k[bq]  = q / (BN / 4);
        b_n4[bq] = (q % (BN / 4)) << 2;
    }

    const int tr0 = (tid >> 4) * TM;
    const int tc0 = (tid & 15) * TN;

    float4 ra[AQ], rb[BQ];

    auto load_chunk = [&](int k0) {
        const int kq  = k0 / CIN;
        const int cib = k0 % CIN;
        const int ky  = kq / KS;
        const int kx  = kq % KS;
        #pragma unroll
        for (int aq = 0; aq < AQ; aq++) {
            const int iy = aoy[aq] * STRIDE + ky - PAD;
            const int ix = aox[aq] * STRIDE + kx - PAD;
            float4 v = make_float4(0.f, 0.f, 0.f, 0.f);
            if (KS == 1 || (iy >= 0 && iy < HIN && ix >= 0 && ix < WIN))
                v = *reinterpret_cast<const float4*>(
                    in + ((size_t)(iy * WIN + ix) * CIN + cib + a_k4[aq]));
            ra[aq] = v;
        }
        #pragma unroll
        for (int bq = 0; bq < BQ; bq++)
            rb[bq] = *reinterpret_cast<const float4*>(
                wgt + (size_t)(k0 + b_k[bq]) * COUT + bn + b_n4[bq]);
    };
    auto store_chunk = [&](int w) {
        #pragma unroll
        for (int aq = 0; aq < AQ; aq++) {
            As[w][a_k4[aq] + 0][a_m[aq]] = ra[aq].x;
            As[w][a_k4[aq] + 1][a_m[aq]] = ra[aq].y;
            As[w][a_k4[aq] + 2][a_m[aq]] = ra[aq].z;
            As[w][a_k4[aq] + 3][a_m[aq]] = ra[aq].w;
        }
        #pragma unroll
        for (int bq = 0; bq < BQ; bq++)
            *reinterpret_cast<float4*>(&Bs[w][b_k[bq]][b_n4[bq]]) = rb[bq];
    };

    float acc[TM][TN] = {};

    load_chunk(kbase);
    store_chunk(0);
    __syncthreads();

    int db = 0;
    for (int c = 0; c < NCH; c++) {
        if (c + 1 < NCH) load_chunk(kbase + (c + 1) * 16);

        #pragma unroll
        for (int kk = 0; kk < 16; kk++) {
            float a[TM], b[TN];
            #pragma unroll
            for (int i = 0; i < TM; i += 4) {
                const float4 v = *reinterpret_cast<const float4*>(&As[db][kk][tr0 + i]);
                a[i] = v.x; a[i + 1] = v.y; a[i + 2] = v.z; a[i + 3] = v.w;
            }
            #pragma unroll
            for (int j = 0; j < TN; j += 4) {
                const float4 v = *reinterpret_cast<const float4*>(&Bs[db][kk][tc0 + j]);
                b[j] = v.x; b[j + 1] = v.y; b[j + 2] = v.z; b[j + 3] = v.w;
            }
            #pragma unroll
            for (int i = 0; i < TM; i++)
                #pragma unroll
                for (int j = 0; j < TN; j++)
                    acc[i][j] = fmaf(a[i], b[j], acc[i][j]);
        }

        if (c + 1 < NCH) store_chunk(db ^ 1);
        __syncthreads();
        db ^= 1;
    }

    // epilogue
    if (SPLITK > 1) {
        float* o = out + (size_t)blockIdx.z * MTOT * COUT;
        #pragma unroll
        for (int i = 0; i < TM; i++) {
            const int m = bm + tr0 + i;
            #pragma unroll
            for (int j = 0; j < TN; j += 4) {
                const float4 r = make_float4(acc[i][j], acc[i][j+1], acc[i][j+2], acc[i][j+3]);
                *reinterpret_cast<float4*>(o + (size_t)m * COUT + bn + tc0 + j) = r;
            }
        }
    } else {
        #pragma unroll
        for (int i = 0; i < TM; i++) {
            const int m  = bm + tr0 + i;
            const int oy = m / WOUT;
            const int ox = m % WOUT;
            #pragma unroll
            for (int j = 0; j < TN; j += 4) {
                float4 r = make_float4(acc[i][j], acc[i][j+1], acc[i][j+2], acc[i][j+3]);
                if (ADDUP2) {
                    const float4 u = *reinterpret_cast<const float4*>(
                        up + ((size_t)((oy >> 1) * (WOUT >> 1) + (ox >> 1)) * COUT + bn + tc0 + j));
                    r.x += u.x; r.y += u.y; r.z += u.z; r.w += u.w;
                }
                if (RELU) {
                    r.x = fmaxf(r.x, 0.f); r.y = fmaxf(r.y, 0.f);
                    r.z = fmaxf(r.z, 0.f); r.w = fmaxf(r.w, 0.f);
                }
                *reinterpret_cast<float4*>(out + (size_t)m * COUT + bn + tc0 + j) = r;
            }
        }
    }
}

// ---------------- split-K combine (+optional relu) ----------------
template<bool RELU, int SPLIT>
__global__ __launch_bounds__(256) void combine_k(
    const float* __restrict__ part, float* __restrict__ out, int n4)
{
    const int i = blockIdx.x * blockDim.x + threadIdx.x;
    if (i >= n4) return;
    float4 s = reinterpret_cast<const float4*>(part)[i];
    #pragma unroll
    for (int z = 1; z < SPLIT; z++) {
        const float4 v = reinterpret_cast<const float4*>(part)[i + (size_t)z * n4];
        s.x += v.x; s.y += v.y; s.z += v.z; s.w += v.w;
    }
    if (RELU) {
        s.x = fmaxf(s.x, 0.f); s.y = fmaxf(s.y, 0.f);
        s.z = fmaxf(s.z, 0.f); s.w = fmaxf(s.w, 0.f);
    }
    reinterpret_cast<float4*>(out)[i] = s;
}

// ---------------- stem: 7x7 s2, Cin=3 -> 64, relu ----------------
__global__ __launch_bounds__(512) void stem_kernel(
    const float* __restrict__ in, const float* __restrict__ w, float* __restrict__ out)
{
    __shared__ float ws[7*7*3*64];
    for (int i = threadIdx.y * 64 + threadIdx.x; i < 7*7*3*64; i += 512)
        ws[i] = w[i];
    __syncthreads();

    const int co = threadIdx.x;
    #pragma unroll
    for (int pp = 0; pp < 2; pp++) {
        const int p  = blockIdx.x * 16 + threadIdx.y * 2 + pp;
        const int oy = p >> 8;
        const int ox = p & 255;
        float acc = 0.f;
        #pragma unroll
        for (int ky = 0; ky < 7; ky++) {
            const int iy = oy * 2 + ky - 2;
            if (iy < 0 || iy >= 512) continue;
            #pragma unroll
            for (int kx = 0; kx < 7; kx++) {
                const int ix = ox * 2 + kx - 2;
                if (ix < 0 || ix >= 512) continue;
                const float* ip = in + (size_t)(iy * 512 + ix) * 3;
                const float* wp = ws + ((ky * 7 + kx) * 3) * 64 + co;
                acc = fmaf(ip[0], wp[0],   acc);
                acc = fmaf(ip[1], wp[64],  acc);
                acc = fmaf(ip[2], wp[128], acc);
            }
        }
        out[(size_t)p * 64 + co] = fmaxf(acc, 0.f);
    }
}

// ---------------- obj head (1x1, COUT=1) + sigmoid ----------------
__global__ __launch_bounds__(256) void obj_kernel(
    const float* __restrict__ t, const float* __restrict__ wobj, float* __restrict__ scores)
{
    const int p = blockIdx.x * 8 + (threadIdx.x >> 5);
    const int lane = threadIdx.x & 31;
    const float* tp = t + (size_t)p * 256;
    float acc = 0.f;
    #pragma unroll
    for (int c = 0; c < 256; c += 32)
        acc = fmaf(tp[c + lane], wobj[c + lane], acc);
    #pragma unroll
    for (int off = 16; off > 0; off >>= 1)
        acc += __shfl_xor_sync(0xFFFFFFFFu, acc, off);
    if (lane == 0)
        scores[p] = 1.f / (1.f + expf(-acc));
}

// ---------------- greedy NMS, 100 iterations, 4096 candidates ----------------
__global__ __launch_bounds__(1024) void nms_kernel(
    const float* __restrict__ scores, float* __restrict__ out)
{
    const int tid = threadIdx.x;
    float sw[4], by1[4], bx1[4], by2[4], bx2[4], bar[4];
    #pragma unroll
    for (int t = 0; t < 4; t++) {
        const int j = tid + t * 1024;
        sw[t] = scores[j];
        const float cy = (float)(j & 63) * (1.0f / 63.0f);
        const float cx = (float)(j >> 6) * (1.0f / 63.0f);
        by1[t] = fmaxf(cy - 0.05f, 0.f);
        bx1[t] = fmaxf(cx - 0.05f, 0.f);
        by2[t] = fminf(cy + 0.05f, 1.f);
        bx2[t] = fminf(cx + 0.05f, 1.f);
        bar[t] = (by2[t] - by1[t]) * (bx2[t] - bx1[t]);
    }

    __shared__ float s_v[32];
    __shared__ int   s_i[32];
    __shared__ float s_bestv;
    __shared__ int   s_besti;

    const int lane = tid & 31;
    const int warp = tid >> 5;

    for (int it = 0; it < 100; it++) {
        float bv = sw[0];
        int   bi = tid;
        #pragma unroll
        for (int t = 1; t < 4; t++) {
            const int j = tid + t * 1024;
            if (sw[t] > bv) { bv = sw[t]; bi = j; }
        }
        #pragma unroll
        for (int off = 16; off > 0; off >>= 1) {
            const float ov = __shfl_down_sync(0xFFFFFFFFu, bv, off);
            const int   oi = __shfl_down_sync(0xFFFFFFFFu, bi, off);
            if (ov > bv || (ov == bv && oi < bi)) { bv = ov; bi = oi; }
        }
        if (lane == 0) { s_v[warp] = bv; s_i[warp] = bi; }
        __syncthreads();
        if (warp == 0) {
            bv = s_v[lane]; bi = s_i[lane];
            #pragma unroll
            for (int off = 16; off > 0; off >>= 1) {
                const float ov = __shfl_down_sync(0xFFFFFFFFu, bv, off);
                const int   oi = __shfl_down_sync(0xFFFFFFFFu, bi, off);
                if (ov > bv || (ov == bv && oi < bi)) { bv = ov; bi = oi; }
            }
            if (lane == 0) { s_bestv = bv; s_besti = bi; }
        }
        __syncthreads();

        const float bestv = s_bestv;
        const int   besti = s_besti;
        const float bcy = (float)(besti & 63) * (1.0f / 63.0f);
        const float bcx = (float)(besti >> 6) * (1.0f / 63.0f);
        const float y1b = fmaxf(bcy - 0.05f, 0.f);
        const float x1b = fmaxf(bcx - 0.05f, 0.f);
        const float y2b = fminf(bcy + 0.05f, 1.f);
        const float x2b = fminf(bcx + 0.05f, 1.f);
        const float areab = (y2b - y1b) * (x2b - x1b);
        const bool valid = bestv > -5e29f;

        if (tid == 0) {
            out[it * 4 + 0] = valid ? y1b : 0.f;
            out[it * 4 + 1] = valid ? x1b : 0.f;
            out[it * 4 + 2] = valid ? y2b : 0.f;
            out[it * 4 + 3] = valid ? x2b : 0.f;
            out[400 + it]   = valid ? bestv : 0.f;
        }

        #pragma unroll
        for (int t = 0; t < 4; t++) {
            const float yy1 = fmaxf(y1b, by1[t]);
            const float xx1 = fmaxf(x1b, bx1[t]);
            const float yy2 = fminf(y2b, by2[t]);
            const float xx2 = fminf(x2b, bx2[t]);
            const float inter = fmaxf(yy2 - yy1, 0.f) * fmaxf(xx2 - xx1, 0.f);
            const float iou = inter / (areab + bar[t] - inter + 1e-9f);
            if (iou > 0.5f) sw[t] = -1e30f;
        }
        __syncthreads();
    }
}

// ---------------- orchestration ----------------
extern "C" void kernel_launch(void* const* d_in, const int* in_sizes, int n_in,
                              void* d_out, int out_size)
{
    (void)in_sizes; (void)n_in; (void)out_size;
    const float* inp    = (const float*)d_in[0];
    const float* w_stem = (const float*)d_in[1];
    const float* w_c2   = (const float*)d_in[2];
    const float* w_c3   = (const float*)d_in[3];
    const float* w_c4   = (const float*)d_in[4];
    const float* w_c5   = (const float*)d_in[5];
    const float* l3     = (const float*)d_in[6];
    const float* l4     = (const float*)d_in[7];
    const float* l5     = (const float*)d_in[8];
    const float* o3     = (const float*)d_in[9];
    const float* w_rpn  = (const float*)d_in[12];
    const float* w_obj  = (const float*)d_in[13];
    float* out = (float*)d_out;

    void *p_s, *p_c2, *p_c3, *p_c4, *p_c5, *p_p5, *p_p4, *p_p3, *p_p3o, *p_t, *p_sc, *p_c5p, *p_p5p;
    cudaGetSymbolAddress(&p_s,   g_s);
    cudaGetSymbolAddress(&p_c2,  g_c2);
    cudaGetSymbolAddress(&p_c3,  g_c3);
    cudaGetSymbolAddress(&p_c4,  g_c4);
    cudaGetSymbolAddress(&p_c5,  g_c5);
    cudaGetSymbolAddress(&p_p5,  g_p5);
    cudaGetSymbolAddress(&p_p4,  g_p4);
    cudaGetSymbolAddress(&p_p3,  g_p3);
    cudaGetSymbolAddress(&p_p3o, g_p3o);
    cudaGetSymbolAddress(&p_t,   g_t);
    cudaGetSymbolAddress(&p_sc,  g_sc);
    cudaGetSymbolAddress(&p_c5p, g_c5p);
    cudaGetSymbolAddress(&p_p5p, g_p5p);
    float* s_   = (float*)p_s;
    float* c2   = (float*)p_c2;
    float* c3   = (float*)p_c3;
    float* c4   = (float*)p_c4;
    float* c5   = (float*)p_c5;
    float* p5   = (float*)p_p5;
    float* p4   = (float*)p_p4;
    float* p3   = (float*)p_p3;
    float* p3o  = (float*)p_p3o;
    float* tb   = (float*)p_t;
    float* sc   = (float*)p_sc;
    float* c5p  = (float*)p_c5p;
    float* p5p  = (float*)p_p5p;

    // backbone
    stem_kernel<<<4096, dim3(64, 8)>>>(inp, w_stem, s_);
    conv_gemm_k<3, 2, 256, 256,   64,  256, true,  false, 128,  64, 1><<<dim3(128, 4, 1), 256>>>(s_,  w_c2, nullptr, c2);
    conv_gemm_k<3, 2, 128, 128,  256,  512, true,  false, 128,  64, 1><<<dim3( 32, 8, 1), 256>>>(c2,  w_c3, nullptr, c3);
    conv_gemm_k<3, 2,  64,  64,  512, 1024, true,  false,  64, 128, 1><<<dim3( 16, 8, 1), 256>>>(c3,  w_c4, nullptr, c4);
    // c5 split-K=2 (M=256 only -> keep the chip full)
    conv_gemm_k<3, 2,  32,  32, 1024, 2048, false, false,  64, 128, 2><<<dim3(  4,16, 2), 256>>>(c4,  w_c5, nullptr, c5p);
    combine_k<true, 2><<<512, 256>>>(c5p, c5, 256 * 2048 / 4);
    // FPN (only the p3 path is live downstream)
    conv_gemm_k<1, 1,  16,  16, 2048,  256, false, false,  64,  64, 4><<<dim3(  4, 4, 4), 256>>>(c5,  l5,   nullptr, p5p);
    combine_k<false, 4><<<64, 256>>>(p5p, p5, 256 * 256 / 4);
    conv_gemm_k<1, 1,  32,  32, 1024,  256, false, true,   64,  64, 1><<<dim3( 16, 4, 1), 256>>>(c4,  l4,   p5,  p4);
    conv_gemm_k<1, 1,  64,  64,  512,  256, false, true,  128,  64, 1><<<dim3( 32, 4, 1), 256>>>(c3,  l3,   p4,  p3);
    conv_gemm_k<3, 1,  64,  64,  256,  256, false, false, 128,  64, 1><<<dim3( 32, 4, 1), 256>>>(p3,  o3,   nullptr, p3o);
    // RPN on p3 only (obj head is the only consumer)
    conv_gemm_k<3, 1,  64,  64,  256,  256, true,  false, 128,  64, 1><<<dim3( 32, 4, 1), 256>>>(p3o, w_rpn, nullptr, tb);
    obj_kernel<<<512, 256>>>(tb, w_obj, sc);
    nms_kernel<<<1, 1024>>>(sc, out);
}

// round 3
// speedup vs baseline: 1.3787x; 1.2346x over previous
#include <cuda_runtime.h>
#include <math.h>

// ---------------- scratch (device globals; no allocation allowed) ----------------
__device__ float g_s  [256*256*64];
__device__ float g_c2 [128*128*256];
__device__ float g_c3 [64*64*512];
__device__ float g_c4 [32*32*1024];
__device__ float g_c5 [16*16*2048];
__device__ float g_p5 [16*16*256];
__device__ float g_p4 [32*32*256];
__device__ float g_p3 [64*64*256];
__device__ float g_p3o[64*64*256];
__device__ float g_t  [64*64*256];
__device__ float g_sc [64*64];
__device__ float g_c5p[2*256*2048];   // split-K partials for c5
__device__ float g_p5p[8*256*256];    // split-K partials for l5

// ---------------- implicit-GEMM conv (NHWC, HWIO, SAME), double-buffered ----------------
// M = HOUT*WOUT, N = COUT, K = KS*KS*CIN. 256 threads as 16x16 grid.
// Micro-tile TM x TN, TM/TN in {4,8}; 8-wide dims split into 2 groups of 4
// offset by BM/2 (resp BN/2) => all compute LDS are broadcast or conflict-free.
template<int KS, int STRIDE, int HIN, int WIN, int CIN, int COUT,
         bool RELU, bool ADDUP2, int BM, int BN, int SPLITK>
__global__ __launch_bounds__(256) void conv_gemm_k(
    const float* __restrict__ in, const float* __restrict__ wgt,
    const float* __restrict__ up, float* __restrict__ out)
{
    constexpr int HOUT = (HIN + STRIDE - 1) / STRIDE;
    constexpr int WOUT = (WIN + STRIDE - 1) / STRIDE;
    constexpr int PTOTC = (HOUT - 1) * STRIDE + KS - HIN;
    constexpr int PAD  = (PTOTC > 0 ? PTOTC : 0) / 2;
    constexpr int K    = KS * KS * CIN;
    constexpr int KSEG = K / SPLITK;
    constexpr int NCH  = KSEG / 16;
    constexpr int TM   = BM / 16;
    constexpr int TN   = BN / 16;
    constexpr int RG   = TM / 4;      // row groups (1 or 2)
    constexpr int CG   = TN / 4;      // col groups (1 or 2)
    constexpr int AQ   = BM / 64;     // A float4 quads per thread
    constexpr int BQ   = BN / 64;     // B float4 quads per thread
    constexpr int MTOT = HOUT * WOUT;
    constexpr int ASTR = BM + 4;      // padded A row stride (keeps 16B align, kills 4-way)

    __shared__ float As[2][16][ASTR];
    __shared__ float Bs[2][16][BN];

    const int tid = threadIdx.x;
    const int bm = blockIdx.x * BM;
    const int bn = blockIdx.y * BN;
    const int kbase = blockIdx.z * KSEG;

    // loader mappings
    int a_m[AQ], a_k4[AQ], aoy[AQ], aox[AQ];
    #pragma unroll
    for (int aq = 0; aq < AQ; aq++) {
        const int q = tid + aq * 256;
        a_m[aq]  = q >> 2;
        a_k4[aq] = (q & 3) << 2;
        const int am = bm + a_m[aq];
        aoy[aq] = am / WOUT;
        aox[aq] = am % WOUT;
    }
    int b_k[BQ], b_n4[BQ];
    #pragma unroll
    for (int bq = 0; bq < BQ; bq++) {
        const int q = tid + bq * 256;
        b_k[bq]  = q / (BN / 4);
        b_n4[bq] = (q % (BN / 4)) << 2;
    }

    const int tr0 = (tid >> 4) << 2;   // 0..60
    const int tc0 = (tid & 15) << 2;   // 0..60

    float4 ra[AQ], rb[BQ];

    auto load_chunk = [&](int k0) {
        const int kq  = k0 / CIN;
        const int cib = k0 % CIN;
        const int ky  = kq / KS;
        const int kx  = kq % KS;
        #pragma unroll
        for (int aq = 0; aq < AQ; aq++) {
            const int iy = aoy[aq] * STRIDE + ky - PAD;
            const int ix = aox[aq] * STRIDE + kx - PAD;
            float4 v = make_float4(0.f, 0.f, 0.f, 0.f);
            if (KS == 1 || (iy >= 0 && iy < HIN && ix >= 0 && ix < WIN))
                v = *reinterpret_cast<const float4*>(
                    in + ((size_t)(iy * WIN + ix) * CIN + cib + a_k4[aq]));
            ra[aq] = v;
        }
        #pragma unroll
        for (int bq = 0; bq < BQ; bq++)
            rb[bq] = *reinterpret_cast<const float4*>(
                wgt + (size_t)(k0 + b_k[bq]) * COUT + bn + b_n4[bq]);
    };
    auto store_chunk = [&](int w) {
        #pragma unroll
        for (int aq = 0; aq < AQ; aq++) {
            As[w][a_k4[aq] + 0][a_m[aq]] = ra[aq].x;
            As[w][a_k4[aq] + 1][a_m[aq]] = ra[aq].y;
            As[w][a_k4[aq] + 2][a_m[aq]] = ra[aq].z;
            As[w][a_k4[aq] + 3][a_m[aq]] = ra[aq].w;
        }
        #pragma unroll
        for (int bq = 0; bq < BQ; bq++)
            *reinterpret_cast<float4*>(&Bs[w][b_k[bq]][b_n4[bq]]) = rb[bq];
    };

    float acc[TM][TN] = {};

    load_chunk(kbase);
    store_chunk(0);
    __syncthreads();

    int db = 0;
    for (int c = 0; c < NCH; c++) {
        if (c + 1 < NCH) load_chunk(kbase + (c + 1) * 16);

        #pragma unroll
        for (int kk = 0; kk < 16; kk++) {
            float a[TM], b[TN];
            #pragma unroll
            for (int g = 0; g < RG; g++) {          // broadcast loads
                const float4 v = *reinterpret_cast<const float4*>(
                    &As[db][kk][tr0 + g * (BM / 2)]);
                a[g*4+0] = v.x; a[g*4+1] = v.y; a[g*4+2] = v.z; a[g*4+3] = v.w;
            }
            #pragma unroll
            for (int h = 0; h < CG; h++) {          // conflict-free loads
                const float4 v = *reinterpret_cast<const float4*>(
                    &Bs[db][kk][tc0 + h * (BN / 2)]);
                b[h*4+0] = v.x; b[h*4+1] = v.y; b[h*4+2] = v.z; b[h*4+3] = v.w;
            }
            #pragma unroll
            for (int i = 0; i < TM; i++)
                #pragma unroll
                for (int j = 0; j < TN; j++)
                    acc[i][j] = fmaf(a[i], b[j], acc[i][j]);
        }

        if (c + 1 < NCH) store_chunk(db ^ 1);
        __syncthreads();
        db ^= 1;
    }

    // epilogue
    #pragma unroll
    for (int i = 0; i < TM; i++) {
        const int m  = bm + tr0 + (i >> 2) * (BM / 2) + (i & 3);
        const int oy = m / WOUT;
        const int ox = m % WOUT;
        #pragma unroll
        for (int h = 0; h < CG; h++) {
            const int ncol = bn + tc0 + h * (BN / 2);
            float4 r = make_float4(acc[i][h*4+0], acc[i][h*4+1], acc[i][h*4+2], acc[i][h*4+3]);
            if (SPLITK > 1) {
                float* o = out + (size_t)blockIdx.z * MTOT * COUT;
                *reinterpret_cast<float4*>(o + (size_t)m * COUT + ncol) = r;
            } else {
                if (ADDUP2) {
                    const float4 u = *reinterpret_cast<const float4*>(
                        up + ((size_t)((oy >> 1) * (WOUT >> 1) + (ox >> 1)) * COUT + ncol));
                    r.x += u.x; r.y += u.y; r.z += u.z; r.w += u.w;
                }
                if (RELU) {
                    r.x = fmaxf(r.x, 0.f); r.y = fmaxf(r.y, 0.f);
                    r.z = fmaxf(r.z, 0.f); r.w = fmaxf(r.w, 0.f);
                }
                *reinterpret_cast<float4*>(out + (size_t)m * COUT + ncol) = r;
            }
        }
    }
}

// ---------------- split-K combine (+optional relu) ----------------
template<bool RELU, int SPLIT>
__global__ __launch_bounds__(256) void combine_k(
    const float* __restrict__ part, float* __restrict__ out, int n4)
{
    const int i = blockIdx.x * blockDim.x + threadIdx.x;
    if (i >= n4) return;
    float4 s = reinterpret_cast<const float4*>(part)[i];
    #pragma unroll
    for (int z = 1; z < SPLIT; z++) {
        const float4 v = reinterpret_cast<const float4*>(part)[i + (size_t)z * n4];
        s.x += v.x; s.y += v.y; s.z += v.z; s.w += v.w;
    }
    if (RELU) {
        s.x = fmaxf(s.x, 0.f); s.y = fmaxf(s.y, 0.f);
        s.z = fmaxf(s.z, 0.f); s.w = fmaxf(s.w, 0.f);
    }
    reinterpret_cast<float4*>(out)[i] = s;
}

// ---------------- stem: 7x7 s2, Cin=3 -> 64, relu ----------------
__global__ __launch_bounds__(512) void stem_kernel(
    const float* __restrict__ in, const float* __restrict__ w, float* __restrict__ out)
{
    __shared__ float ws[7*7*3*64];
    for (int i = threadIdx.y * 64 + threadIdx.x; i < 7*7*3*64; i += 512)
        ws[i] = w[i];
    __syncthreads();

    const int co = threadIdx.x;
    #pragma unroll
    for (int pp = 0; pp < 2; pp++) {
        const int p  = blockIdx.x * 16 + threadIdx.y * 2 + pp;
        const int oy = p >> 8;
        const int ox = p & 255;
        float acc = 0.f;
        #pragma unroll
        for (int ky = 0; ky < 7; ky++) {
            const int iy = oy * 2 + ky - 2;
            if (iy < 0 || iy >= 512) continue;
            #pragma unroll
            for (int kx = 0; kx < 7; kx++) {
                const int ix = ox * 2 + kx - 2;
                if (ix < 0 || ix >= 512) continue;
                const float* ip = in + (size_t)(iy * 512 + ix) * 3;
                const float* wp = ws + ((ky * 7 + kx) * 3) * 64 + co;
                acc = fmaf(ip[0], wp[0],   acc);
                acc = fmaf(ip[1], wp[64],  acc);
                acc = fmaf(ip[2], wp[128], acc);
            }
        }
        out[(size_t)p * 64 + co] = fmaxf(acc, 0.f);
    }
}

// ---------------- obj head (1x1, COUT=1) + sigmoid ----------------
__global__ __launch_bounds__(256) void obj_kernel(
    const float* __restrict__ t, const float* __restrict__ wobj, float* __restrict__ scores)
{
    const int p = blockIdx.x * 8 + (threadIdx.x >> 5);
    const int lane = threadIdx.x & 31;
    const float* tp = t + (size_t)p * 256;
    float acc = 0.f;
    #pragma unroll
    for (int c = 0; c < 256; c += 32)
        acc = fmaf(tp[c + lane], wobj[c + lane], acc);
    #pragma unroll
    for (int off = 16; off > 0; off >>= 1)
        acc += __shfl_xor_sync(0xFFFFFFFFu, acc, off);
    if (lane == 0)
        scores[p] = 1.f / (1.f + expf(-acc));
}

// ---------------- greedy NMS, 100 iterations, 4096 candidates ----------------
__global__ __launch_bounds__(1024) void nms_kernel(
    const float* __restrict__ scores, float* __restrict__ out)
{
    const int tid = threadIdx.x;
    float sw[4], by1[4], bx1[4], by2[4], bx2[4], bar[4];
    #pragma unroll
    for (int t = 0; t < 4; t++) {
        const int j = tid + t * 1024;
        sw[t] = scores[j];
        const float cy = (float)(j & 63) * (1.0f / 63.0f);
        const float cx = (float)(j >> 6) * (1.0f / 63.0f);
        by1[t] = fmaxf(cy - 0.05f, 0.f);
        bx1[t] = fmaxf(cx - 0.05f, 0.f);
        by2[t] = fminf(cy + 0.05f, 1.f);
        bx2[t] = fminf(cx + 0.05f, 1.f);
        bar[t] = (by2[t] - by1[t]) * (bx2[t] - bx1[t]);
    }

    __shared__ float s_v[32];
    __shared__ int   s_i[32];
    __shared__ float s_bestv;
    __shared__ int   s_besti;

    const int lane = tid & 31;
    const int warp = tid >> 5;

    for (int it = 0; it < 100; it++) {
        float bv = sw[0];
        int   bi = tid;
        #pragma unroll
        for (int t = 1; t < 4; t++) {
            const int j = tid + t * 1024;
            if (sw[t] > bv) { bv = sw[t]; bi = j; }
        }
        #pragma unroll
        for (int off = 16; off > 0; off >>= 1) {
            const float ov = __shfl_down_sync(0xFFFFFFFFu, bv, off);
            const int   oi = __shfl_down_sync(0xFFFFFFFFu, bi, off);
            if (ov > bv || (ov == bv && oi < bi)) { bv = ov; bi = oi; }
        }
        if (lane == 0) { s_v[warp] = bv; s_i[warp] = bi; }
        __syncthreads();
        if (warp == 0) {
            bv = s_v[lane]; bi = s_i[lane];
            #pragma unroll
            for (int off = 16; off > 0; off >>= 1) {
                const float ov = __shfl_down_sync(0xFFFFFFFFu, bv, off);
                const int   oi = __shfl_down_sync(0xFFFFFFFFu, bi, off);
                if (ov > bv || (ov == bv && oi < bi)) { bv = ov; bi = oi; }
            }
            if (lane == 0) { s_bestv = bv; s_besti = bi; }
        }
        __syncthreads();

        const float bestv = s_bestv;
        const int   besti = s_besti;
        const float bcy = (float)(besti & 63) * (1.0f / 63.0f);
        const float bcx = (float)(besti >> 6) * (1.0f / 63.0f);
        const float y1b = fmaxf(bcy - 0.05f, 0.f);
        const float x1b = fmaxf(bcx - 0.05f, 0.f);
        const float y2b = fminf(bcy + 0.05f, 1.f);
        const float x2b = fminf(bcx + 0.05f, 1.f);
        const float areab = (y2b - y1b) * (x2b - x1b);
        const bool valid = bestv > -5e29f;

        if (tid == 0) {
            out[it * 4 + 0] = valid ? y1b : 0.f;
            out[it * 4 + 1] = valid ? x1b : 0.f;
            out[it * 4 + 2] = valid ? y2b : 0.f;
            out[it * 4 + 3] = valid ? x2b : 0.f;
            out[400 + it]   = valid ? bestv : 0.f;
        }

        #pragma unroll
        for (int t = 0; t < 4; t++) {
            const float yy1 = fmaxf(y1b, by1[t]);
            const float xx1 = fmaxf(x1b, bx1[t]);
            const float yy2 = fminf(y2b, by2[t]);
            const float xx2 = fminf(x2b, bx2[t]);
            const float inter = fmaxf(yy2 - yy1, 0.f) * fmaxf(xx2 - xx1, 0.f);
            const float iou = inter / (areab + bar[t] - inter + 1e-9f);
            if (iou > 0.5f) sw[t] = -1e30f;
        }
        __syncthreads();
    }
}

// ---------------- orchestration ----------------
extern "C" void kernel_launch(void* const* d_in, const int* in_sizes, int n_in,
                              void* d_out, int out_size)
{
    (void)in_sizes; (void)n_in; (void)out_size;
    const float* inp    = (const float*)d_in[0];
    const float* w_stem = (const float*)d_in[1];
    const float* w_c2   = (const float*)d_in[2];
    const float* w_c3   = (const float*)d_in[3];
    const float* w_c4   = (const float*)d_in[4];
    const float* w_c5   = (const float*)d_in[5];
    const float* l3     = (const float*)d_in[6];
    const float* l4     = (const float*)d_in[7];
    const float* l5     = (const float*)d_in[8];
    const float* o3     = (const float*)d_in[9];
    const float* w_rpn  = (const float*)d_in[12];
    const float* w_obj  = (const float*)d_in[13];
    float* out = (float*)d_out;

    void *p_s, *p_c2, *p_c3, *p_c4, *p_c5, *p_p5, *p_p4, *p_p3, *p_p3o, *p_t, *p_sc, *p_c5p, *p_p5p;
    cudaGetSymbolAddress(&p_s,   g_s);
    cudaGetSymbolAddress(&p_c2,  g_c2);
    cudaGetSymbolAddress(&p_c3,  g_c3);
    cudaGetSymbolAddress(&p_c4,  g_c4);
    cudaGetSymbolAddress(&p_c5,  g_c5);
    cudaGetSymbolAddress(&p_p5,  g_p5);
    cudaGetSymbolAddress(&p_p4,  g_p4);
    cudaGetSymbolAddress(&p_p3,  g_p3);
    cudaGetSymbolAddress(&p_p3o, g_p3o);
    cudaGetSymbolAddress(&p_t,   g_t);
    cudaGetSymbolAddress(&p_sc,  g_sc);
    cudaGetSymbolAddress(&p_c5p, g_c5p);
    cudaGetSymbolAddress(&p_p5p, g_p5p);
    float* s_   = (float*)p_s;
    float* c2   = (float*)p_c2;
    float* c3   = (float*)p_c3;
    float* c4   = (float*)p_c4;
    float* c5   = (float*)p_c5;
    float* p5   = (float*)p_p5;
    float* p4   = (float*)p_p4;
    float* p3   = (float*)p_p3;
    float* p3o  = (float*)p_p3o;
    float* tb   = (float*)p_t;
    float* sc   = (float*)p_sc;
    float* c5p  = (float*)p_c5p;
    float* p5p  = (float*)p_p5p;

    // backbone
    stem_kernel<<<4096, dim3(64, 8)>>>(inp, w_stem, s_);
    conv_gemm_k<3, 2, 256, 256,   64,  256, true,  false, 128, 64, 1><<<dim3(128, 4, 1), 256>>>(s_,  w_c2, nullptr, c2);
    conv_gemm_k<3, 2, 128, 128,  256,  512, true,  false, 128, 64, 1><<<dim3( 32, 8, 1), 256>>>(c2,  w_c3, nullptr, c3);
    conv_gemm_k<3, 2,  64,  64,  512, 1024, true,  false,  64, 64, 1><<<dim3( 16,16, 1), 256>>>(c3,  w_c4, nullptr, c4);
    // c5 split-K=2 (M=256 only -> keep the chip full)
    conv_gemm_k<3, 2,  32,  32, 1024, 2048, false, false,  64, 64, 2><<<dim3(  4,32, 2), 256>>>(c4,  w_c5, nullptr, c5p);
    combine_k<true, 2><<<512, 256>>>(c5p, c5, 256 * 2048 / 4);
    // FPN (only the p3 path is live downstream)
    conv_gemm_k<1, 1,  16,  16, 2048,  256, false, false,  64, 64, 8><<<dim3(  4, 4, 8), 256>>>(c5,  l5,   nullptr, p5p);
    combine_k<false, 8><<<64, 256>>>(p5p, p5, 256 * 256 / 4);
    conv_gemm_k<1, 1,  32,  32, 1024,  256, false, true,   64, 64, 1><<<dim3( 16, 4, 1), 256>>>(c4,  l4,   p5,  p4);
    conv_gemm_k<1, 1,  64,  64,  512,  256, false, true,   64, 64, 1><<<dim3( 64, 4, 1), 256>>>(c3,  l3,   p4,  p3);
    conv_gemm_k<3, 1,  64,  64,  256,  256, false, false,  64, 64, 1><<<dim3( 64, 4, 1), 256>>>(p3,  o3,   nullptr, p3o);
    // RPN on p3 only (obj head is the only consumer)
    conv_gemm_k<3, 1,  64,  64,  256,  256, true,  false,  64, 64, 1><<<dim3( 64, 4, 1), 256>>>(p3o, w_rpn, nullptr, tb);
    obj_kernel<<<512, 256>>>(tb, w_obj, sc);
    nms_kernel<<<1, 1024>>>(sc, out);
}

// round 4
// speedup vs baseline: 1.5911x; 1.1541x over previous
#include <cuda_runtime.h>
#include <math.h>

// ---------------- scratch (device globals; no allocation allowed) ----------------
__device__ float g_s  [256*256*64];
__device__ float g_c2 [128*128*256];
__device__ float g_c3 [64*64*512];
__device__ float g_c4 [32*32*1024];
__device__ float g_c5 [16*16*2048];
__device__ float g_p5 [16*16*256];
__device__ float g_p4 [32*32*256];
__device__ float g_p3 [64*64*256];
__device__ float g_p3o[64*64*256];
__device__ float g_t  [64*64*256];
__device__ float g_sc [64*64];
__device__ float g_c4p[2*1024*1024];  // split-K partials for c4
__device__ float g_c5p[4*256*2048];   // split-K partials for c5
__device__ float g_p5p[8*256*256];    // split-K partials for l5
__device__ float g_op [2*4096*256];   // split-K partials for o3 / rpn (reused)

// ---------------- implicit-GEMM conv (NHWC, HWIO, SAME), double-buffered ----------------
// 256 threads as 16x16 grid. TM,TN in {4,8}; 8-wide dims split into 2 groups of 4
// offset by BM/2 (resp BN/2): A compute loads are 2-line broadcasts, B loads are
// 16 contiguous float4s -> conflict-free.
template<int KS, int STRIDE, int HIN, int WIN, int CIN, int COUT,
         bool RELU, bool ADDUP2, int BM, int BN, int SPLITK>
__global__ __launch_bounds__(256) void conv_gemm_k(
    const float* __restrict__ in, const float* __restrict__ wgt,
    const float* __restrict__ up, float* __restrict__ out)
{
    constexpr int HOUT = (HIN + STRIDE - 1) / STRIDE;
    constexpr int WOUT = (WIN + STRIDE - 1) / STRIDE;
    constexpr int PTOTC = (HOUT - 1) * STRIDE + KS - HIN;
    constexpr int PAD  = (PTOTC > 0 ? PTOTC : 0) / 2;
    constexpr int K    = KS * KS * CIN;
    constexpr int KSEG = K / SPLITK;
    constexpr int NCH  = KSEG / 16;
    constexpr int TM   = BM / 16;
    constexpr int TN   = BN / 16;
    constexpr int RG   = TM / 4;
    constexpr int CG   = TN / 4;
    constexpr int AQ   = BM / 64;
    constexpr int BQ   = BN / 64;
    constexpr int MTOT = HOUT * WOUT;
    constexpr int ASTR = BM + 4;

    __shared__ float As[2][16][ASTR];
    __shared__ float Bs[2][16][BN];

    const int tid = threadIdx.x;
    const int bm = blockIdx.x * BM;
    const int bn = blockIdx.y * BN;
    const int kbase = blockIdx.z * KSEG;

    int a_m[AQ], a_k4[AQ], aoy[AQ], aox[AQ];
    #pragma unroll
    for (int aq = 0; aq < AQ; aq++) {
        const int q = tid + aq * 256;
        a_m[aq]  = q >> 2;
        a_k4[aq] = (q & 3) << 2;
        const int am = bm + a_m[aq];
        aoy[aq] = am / WOUT;
        aox[aq] = am % WOUT;
    }
    int b_k[BQ], b_n4[BQ];
    #pragma unroll
    for (int bq = 0; bq < BQ; bq++) {
        const int q = tid + bq * 256;
        b_k[bq]  = q / (BN / 4);
        b_n4[bq] = (q % (BN / 4)) << 2;
    }

    const int tr0 = (tid >> 4) << 2;
    const int tc0 = (tid & 15) << 2;

    float4 ra[AQ], rb[BQ];

    auto load_chunk = [&](int k0) {
        const int kq  = k0 / CIN;
        const int cib = k0 % CIN;
        const int ky  = kq / KS;
        const int kx  = kq % KS;
        #pragma unroll
        for (int aq = 0; aq < AQ; aq++) {
            const int iy = aoy[aq] * STRIDE + ky - PAD;
            const int ix = aox[aq] * STRIDE + kx - PAD;
            float4 v = make_float4(0.f, 0.f, 0.f, 0.f);
            if (KS == 1 || (iy >= 0 && iy < HIN && ix >= 0 && ix < WIN))
                v = *reinterpret_cast<const float4*>(
                    in + ((size_t)(iy * WIN + ix) * CIN + cib + a_k4[aq]));
            ra[aq] = v;
        }
        #pragma unroll
        for (int bq = 0; bq < BQ; bq++)
            rb[bq] = *reinterpret_cast<const float4*>(
                wgt + (size_t)(k0 + b_k[bq]) * COUT + bn + b_n4[bq]);
    };
    auto store_chunk = [&](int w) {
        #pragma unroll
        for (int aq = 0; aq < AQ; aq++) {
            As[w][a_k4[aq] + 0][a_m[aq]] = ra[aq].x;
            As[w][a_k4[aq] + 1][a_m[aq]] = ra[aq].y;
            As[w][a_k4[aq] + 2][a_m[aq]] = ra[aq].z;
            As[w][a_k4[aq] + 3][a_m[aq]] = ra[aq].w;
        }
        #pragma unroll
        for (int bq = 0; bq < BQ; bq++)
            *reinterpret_cast<float4*>(&Bs[w][b_k[bq]][b_n4[bq]]) = rb[bq];
    };

    float acc[TM][TN] = {};

    load_chunk(kbase);
    store_chunk(0);
    __syncthreads();

    int db = 0;
    for (int c = 0; c < NCH; c++) {
        if (c + 1 < NCH) load_chunk(kbase + (c + 1) * 16);

        #pragma unroll
        for (int kk = 0; kk < 16; kk++) {
            float a[TM], b[TN];
            #pragma unroll
            for (int g = 0; g < RG; g++) {
                const float4 v = *reinterpret_cast<const float4*>(
                    &As[db][kk][tr0 + g * (BM / 2)]);
                a[g*4+0] = v.x; a[g*4+1] = v.y; a[g*4+2] = v.z; a[g*4+3] = v.w;
            }
            #pragma unroll
            for (int h = 0; h < CG; h++) {
                const float4 v = *reinterpret_cast<const float4*>(
                    &Bs[db][kk][tc0 + h * (BN / 2)]);
                b[h*4+0] = v.x; b[h*4+1] = v.y; b[h*4+2] = v.z; b[h*4+3] = v.w;
            }
            #pragma unroll
            for (int i = 0; i < TM; i++)
                #pragma unroll
                for (int j = 0; j < TN; j++)
                    acc[i][j] = fmaf(a[i], b[j], acc[i][j]);
        }

        if (c + 1 < NCH) store_chunk(db ^ 1);
        __syncthreads();
        db ^= 1;
    }

    // epilogue
    #pragma unroll
    for (int i = 0; i < TM; i++) {
        const int m  = bm + tr0 + (i >> 2) * (BM / 2) + (i & 3);
        const int oy = m / WOUT;
        const int ox = m % WOUT;
        #pragma unroll
        for (int h = 0; h < CG; h++) {
            const int ncol = bn + tc0 + h * (BN / 2);
            float4 r = make_float4(acc[i][h*4+0], acc[i][h*4+1], acc[i][h*4+2], acc[i][h*4+3]);
            if (SPLITK > 1) {
                float* o = out + (size_t)blockIdx.z * MTOT * COUT;
                *reinterpret_cast<float4*>(o + (size_t)m * COUT + ncol) = r;
            } else {
                if (ADDUP2) {
                    const float4 u = *reinterpret_cast<const float4*>(
                        up + ((size_t)((oy >> 1) * (WOUT >> 1) + (ox >> 1)) * COUT + ncol));
                    r.x += u.x; r.y += u.y; r.z += u.z; r.w += u.w;
                }
                if (RELU) {
                    r.x = fmaxf(r.x, 0.f); r.y = fmaxf(r.y, 0.f);
                    r.z = fmaxf(r.z, 0.f); r.w = fmaxf(r.w, 0.f);
                }
                *reinterpret_cast<float4*>(out + (size_t)m * COUT + ncol) = r;
            }
        }
    }
}

// ---------------- split-K combine (+optional relu) ----------------
template<bool RELU, int SPLIT>
__global__ __launch_bounds__(256) void combine_k(
    const float* __restrict__ part, float* __restrict__ out, int n4)
{
    const int i = blockIdx.x * blockDim.x + threadIdx.x;
    if (i >= n4) return;
    float4 s = reinterpret_cast<const float4*>(part)[i];
    #pragma unroll
    for (int z = 1; z < SPLIT; z++) {
        const float4 v = reinterpret_cast<const float4*>(part)[i + (size_t)z * n4];
        s.x += v.x; s.y += v.y; s.z += v.z; s.w += v.w;
    }
    if (RELU) {
        s.x = fmaxf(s.x, 0.f); s.y = fmaxf(s.y, 0.f);
        s.z = fmaxf(s.z, 0.f); s.w = fmaxf(s.w, 0.f);
    }
    reinterpret_cast<float4*>(out)[i] = s;
}

// ---------------- stem: 7x7 s2, Cin=3 -> 64, relu ----------------
__global__ __launch_bounds__(512) void stem_kernel(
    const float* __restrict__ in, const float* __restrict__ w, float* __restrict__ out)
{
    __shared__ float ws[7*7*3*64];
    for (int i = threadIdx.y * 64 + threadIdx.x; i < 7*7*3*64; i += 512)
        ws[i] = w[i];
    __syncthreads();

    const int co = threadIdx.x;
    #pragma unroll
    for (int pp = 0; pp < 2; pp++) {
        const int p  = blockIdx.x * 16 + threadIdx.y * 2 + pp;
        const int oy = p >> 8;
        const int ox = p & 255;
        float acc = 0.f;
        #pragma unroll
        for (int ky = 0; ky < 7; ky++) {
            const int iy = oy * 2 + ky - 2;
            if (iy < 0 || iy >= 512) continue;
            #pragma unroll
            for (int kx = 0; kx < 7; kx++) {
                const int ix = ox * 2 + kx - 2;
                if (ix < 0 || ix >= 512) continue;
                const float* ip = in + (size_t)(iy * 512 + ix) * 3;
                const float* wp = ws + ((ky * 7 + kx) * 3) * 64 + co;
                acc = fmaf(ip[0], wp[0],   acc);
                acc = fmaf(ip[1], wp[64],  acc);
                acc = fmaf(ip[2], wp[128], acc);
            }
        }
        out[(size_t)p * 64 + co] = fmaxf(acc, 0.f);
    }
}

// ---------------- obj head (1x1, COUT=1) + sigmoid ----------------
__global__ __launch_bounds__(256) void obj_kernel(
    const float* __restrict__ t, const float* __restrict__ wobj, float* __restrict__ scores)
{
    const int p = blockIdx.x * 8 + (threadIdx.x >> 5);
    const int lane = threadIdx.x & 31;
    const float* tp = t + (size_t)p * 256;
    float acc = 0.f;
    #pragma unroll
    for (int c = 0; c < 256; c += 32)
        acc = fmaf(tp[c + lane], wobj[c + lane], acc);
    #pragma unroll
    for (int off = 16; off > 0; off >>= 1)
        acc += __shfl_xor_sync(0xFFFFFFFFu, acc, off);
    if (lane == 0)
        scores[p] = 1.f / (1.f + expf(-acc));
}

// ---------------- greedy NMS, 100 iterations, 4096 candidates ----------------
__global__ __launch_bounds__(1024) void nms_kernel(
    const float* __restrict__ scores, float* __restrict__ out)
{
    const int tid = threadIdx.x;
    float sw[4], by1[4], bx1[4], by2[4], bx2[4], bar[4];
    #pragma unroll
    for (int t = 0; t < 4; t++) {
        const int j = tid + t * 1024;
        sw[t] = scores[j];
        const float cy = (float)(j & 63) * (1.0f / 63.0f);
        const float cx = (float)(j >> 6) * (1.0f / 63.0f);
        by1[t] = fmaxf(cy - 0.05f, 0.f);
        bx1[t] = fmaxf(cx - 0.05f, 0.f);
        by2[t] = fminf(cy + 0.05f, 1.f);
        bx2[t] = fminf(cx + 0.05f, 1.f);
        bar[t] = (by2[t] - by1[t]) * (bx2[t] - bx1[t]);
    }

    __shared__ float s_v[32];
    __shared__ int   s_i[32];
    __shared__ float s_bestv;
    __shared__ int   s_besti;

    const int lane = tid & 31;
    const int warp = tid >> 5;

    for (int it = 0; it < 100; it++) {
        float bv = sw[0];
        int   bi = tid;
        #pragma unroll
        for (int t = 1; t < 4; t++) {
            const int j = tid + t * 1024;
            if (sw[t] > bv) { bv = sw[t]; bi = j; }
        }
        #pragma unroll
        for (int off = 16; off > 0; off >>= 1) {
            const float ov = __shfl_down_sync(0xFFFFFFFFu, bv, off);
            const int   oi = __shfl_down_sync(0xFFFFFFFFu, bi, off);
            if (ov > bv || (ov == bv && oi < bi)) { bv = ov; bi = oi; }
        }
        if (lane == 0) { s_v[warp] = bv; s_i[warp] = bi; }
        __syncthreads();
        if (warp == 0) {
            bv = s_v[lane]; bi = s_i[lane];
            #pragma unroll
            for (int off = 16; off > 0; off >>= 1) {
                const float ov = __shfl_down_sync(0xFFFFFFFFu, bv, off);
                const int   oi = __shfl_down_sync(0xFFFFFFFFu, bi, off);
                if (ov > bv || (ov == bv && oi < bi)) { bv = ov; bi = oi; }
            }
            if (lane == 0) { s_bestv = bv; s_besti = bi; }
        }
        __syncthreads();

        const float bestv = s_bestv;
        const int   besti = s_besti;
        const float bcy = (float)(besti & 63) * (1.0f / 63.0f);
        const float bcx = (float)(besti >> 6) * (1.0f / 63.0f);
        const float y1b = fmaxf(bcy - 0.05f, 0.f);
        const float x1b = fmaxf(bcx - 0.05f, 0.f);
        const float y2b = fminf(bcy + 0.05f, 1.f);
        const float x2b = fminf(bcx + 0.05f, 1.f);
        const float areab = (y2b - y1b) * (x2b - x1b);
        const bool valid = bestv > -5e29f;

        if (tid == 0) {
            out[it * 4 + 0] = valid ? y1b : 0.f;
            out[it * 4 + 1] = valid ? x1b : 0.f;
            out[it * 4 + 2] = valid ? y2b : 0.f;
            out[it * 4 + 3] = valid ? x2b : 0.f;
            out[400 + it]   = valid ? bestv : 0.f;
        }

        #pragma unroll
        for (int t = 0; t < 4; t++) {
            const float yy1 = fmaxf(y1b, by1[t]);
            const float xx1 = fmaxf(x1b, bx1[t]);
            const float yy2 = fminf(y2b, by2[t]);
            const float xx2 = fminf(x2b, bx2[t]);
            const float inter = fmaxf(yy2 - yy1, 0.f) * fmaxf(xx2 - xx1, 0.f);
            const float iou = inter / (areab + bar[t] - inter + 1e-9f);
            if (iou > 0.5f) sw[t] = -1e30f;
        }
        __syncthreads();
    }
}

// ---------------- orchestration ----------------
extern "C" void kernel_launch(void* const* d_in, const int* in_sizes, int n_in,
                              void* d_out, int out_size)
{
    (void)in_sizes; (void)n_in; (void)out_size;
    const float* inp    = (const float*)d_in[0];
    const float* w_stem = (const float*)d_in[1];
    const float* w_c2   = (const float*)d_in[2];
    const float* w_c3   = (const float*)d_in[3];
    const float* w_c4   = (const float*)d_in[4];
    const float* w_c5   = (const float*)d_in[5];
    const float* l3     = (const float*)d_in[6];
    const float* l4     = (const float*)d_in[7];
    const float* l5     = (const float*)d_in[8];
    const float* o3     = (const float*)d_in[9];
    const float* w_rpn  = (const float*)d_in[12];
    const float* w_obj  = (const float*)d_in[13];
    float* out = (float*)d_out;

    void *p_s, *p_c2, *p_c3, *p_c4, *p_c5, *p_p5, *p_p4, *p_p3, *p_p3o, *p_t, *p_sc;
    void *p_c4p, *p_c5p, *p_p5p, *p_op;
    cudaGetSymbolAddress(&p_s,   g_s);
    cudaGetSymbolAddress(&p_c2,  g_c2);
    cudaGetSymbolAddress(&p_c3,  g_c3);
    cudaGetSymbolAddress(&p_c4,  g_c4);
    cudaGetSymbolAddress(&p_c5,  g_c5);
    cudaGetSymbolAddress(&p_p5,  g_p5);
    cudaGetSymbolAddress(&p_p4,  g_p4);
    cudaGetSymbolAddress(&p_p3,  g_p3);
    cudaGetSymbolAddress(&p_p3o, g_p3o);
    cudaGetSymbolAddress(&p_t,   g_t);
    cudaGetSymbolAddress(&p_sc,  g_sc);
    cudaGetSymbolAddress(&p_c4p, g_c4p);
    cudaGetSymbolAddress(&p_c5p, g_c5p);
    cudaGetSymbolAddress(&p_p5p, g_p5p);
    cudaGetSymbolAddress(&p_op,  g_op);
    float* s_   = (float*)p_s;
    float* c2   = (float*)p_c2;
    float* c3   = (float*)p_c3;
    float* c4   = (float*)p_c4;
    float* c5   = (float*)p_c5;
    float* p5   = (float*)p_p5;
    float* p4   = (float*)p_p4;
    float* p3   = (float*)p_p3;
    float* p3o  = (float*)p_p3o;
    float* tb   = (float*)p_t;
    float* sc   = (float*)p_sc;
    float* c4p  = (float*)p_c4p;
    float* c5p  = (float*)p_c5p;
    float* p5p  = (float*)p_p5p;
    float* op   = (float*)p_op;

    // backbone
    stem_kernel<<<4096, dim3(64, 8)>>>(inp, w_stem, s_);
    // c2: 16384x256, K=576 -> 128x128 tiles, 256 blocks
    conv_gemm_k<3, 2, 256, 256,   64,  256, true,  false, 128, 128, 1><<<dim3(128, 2, 1), 256>>>(s_, w_c2, nullptr, c2);
    // c3: 4096x512, K=2304 -> 128x64, 256 blocks
    conv_gemm_k<3, 2, 128, 128,  256,  512, true,  false, 128,  64, 1><<<dim3( 32, 8, 1), 256>>>(c2, w_c3, nullptr, c3);
    // c4: 1024x1024, K=4608 -> 128x64 split-K2, 256 blocks
    conv_gemm_k<3, 2,  64,  64,  512, 1024, false, false, 128,  64, 2><<<dim3(  8,16, 2), 256>>>(c3, w_c4, nullptr, c4p);
    combine_k<true, 2><<<1024, 256>>>(c4p, c4, 1024 * 1024 / 4);
    // c5: 256x2048, K=9216 -> 128x64 split-K4, 256 blocks
    conv_gemm_k<3, 2,  32,  32, 1024, 2048, false, false, 128,  64, 4><<<dim3(  2,32, 4), 256>>>(c4, w_c5, nullptr, c5p);
    combine_k<true, 4><<<512, 256>>>(c5p, c5, 256 * 2048 / 4);
    // FPN (only p3 path live)
    conv_gemm_k<1, 1,  16,  16, 2048,  256, false, false,  64,  64, 8><<<dim3(  4, 4, 8), 256>>>(c5, l5, nullptr, p5p);
    combine_k<false, 8><<<64, 256>>>(p5p, p5, 256 * 256 / 4);
    conv_gemm_k<1, 1,  32,  32, 1024,  256, false, true,   64,  64, 1><<<dim3( 16, 4, 1), 256>>>(c4, l4, p5, p4);
    conv_gemm_k<1, 1,  64,  64,  512,  256, false, true,   64,  64, 1><<<dim3( 64, 4, 1), 256>>>(c3, l3, p4, p3);
    // o3: 4096x256, K=2304 -> 128x64 split-K2, 256 blocks
    conv_gemm_k<3, 1,  64,  64,  256,  256, false, false, 128,  64, 2><<<dim3( 32, 4, 2), 256>>>(p3, o3, nullptr, op);
    combine_k<false, 2><<<1024, 256>>>(op, p3o, 4096 * 256 / 4);
    // rpn: same shape, relu in combine
    conv_gemm_k<3, 1,  64,  64,  256,  256, false, false, 128,  64, 2><<<dim3( 32, 4, 2), 256>>>(p3o, w_rpn, nullptr, op);
    combine_k<true, 2><<<1024, 256>>>(op, tb, 4096 * 256 / 4);
    obj_kernel<<<512, 256>>>(tb, w_obj, sc);
    nms_kernel<<<1, 1024>>>(sc, out);
}